// round 1
// baseline (speedup 1.0000x reference)
#include <cuda_runtime.h>
#include <math.h>

#define NTOK 16384          // BATCH * SEQ
#define SEQL 2048
#define NB   8
#define DM   384
#define DI   768
#define DS   16
#define DTR  24
#define XD   56             // DTR + 2*DS
#define XZW  1536           // 2*DI

// ---------------- scratch (static device memory; no allocation) ------------
__device__ float g_xn  [(size_t)NTOK * DM];
__device__ float g_xz  [(size_t)NTOK * XZW];
__device__ float g_xs  [(size_t)NTOK * DI];
__device__ float g_xdbl[(size_t)NTOK * XD];
__device__ float g_dt  [(size_t)NTOK * DI];
__device__ float g_y   [(size_t)NTOK * DI];
__device__ float g_h1  [(size_t)NTOK * DM];
__device__ float g_h2  [(size_t)NTOK * DM];

// ---------------- layernorm: one block per token ---------------------------
__global__ void ln_kernel(const float* __restrict__ in,
                          const float* __restrict__ w,
                          const float* __restrict__ b,
                          float* __restrict__ out)
{
    int row = blockIdx.x;
    const float* x = in + (size_t)row * DM;
    int t = threadIdx.x;               // 128 threads, 3 elems each
    float v[3];
    float s = 0.f;
    #pragma unroll
    for (int i = 0; i < 3; i++) { v[i] = x[t + i * 128]; s += v[i]; }

    __shared__ float red[4];
    #pragma unroll
    for (int o = 16; o > 0; o >>= 1) s += __shfl_xor_sync(0xffffffffu, s, o);
    if ((t & 31) == 0) red[t >> 5] = s;
    __syncthreads();
    float mu = (red[0] + red[1] + red[2] + red[3]) * (1.f / 384.f);

    float q = 0.f;
    #pragma unroll
    for (int i = 0; i < 3; i++) { float d = v[i] - mu; q = fmaf(d, d, q); }
    #pragma unroll
    for (int o = 16; o > 0; o >>= 1) q += __shfl_xor_sync(0xffffffffu, q, o);
    __syncthreads();
    if ((t & 31) == 0) red[t >> 5] = q;
    __syncthreads();
    float var = (red[0] + red[1] + red[2] + red[3]) * (1.f / 384.f);
    float rs = rsqrtf(var + 1e-5f);

    float* o = out + (size_t)row * DM;
    #pragma unroll
    for (int i = 0; i < 3; i++) {
        int c = t + i * 128;
        o[c] = (v[i] - mu) * rs * w[c] + b[c];
    }
}

// ---------------- generic NT SGEMM: C[m,n] = epi( sum_k A[m,k]*B[n,k] ) ----
#define BM 64
#define BN 64
#define BK 16

// epi: 0 = none, 1 = softplus(v + bias[n]), 2 = v + resid[m*ldr + n]
__global__ void gemm_nt(const float* __restrict__ A, int lda,
                        const float* __restrict__ B, int ldb,
                        float* __restrict__ C, int ldc,
                        const float* __restrict__ bias,
                        const float* __restrict__ resid, int ldr,
                        int M, int N, int K, int epi)
{
    __shared__ __align__(16) float As[BK][BM + 4];
    __shared__ __align__(16) float Bs[BK][BN + 4];

    int tid = threadIdx.x;           // 256 threads
    int tx = tid & 15, ty = tid >> 4;
    int m0 = blockIdx.y * BM, n0 = blockIdx.x * BN;

    float acc[4][4] = {};

    for (int k0 = 0; k0 < K; k0 += BK) {
        #pragma unroll
        for (int i = 0; i < (BM * BK) / 256; i++) {
            int idx = tid + i * 256;
            int m = idx >> 4, k = idx & 15;
            int gm = m0 + m, gk = k0 + k;
            As[k][m] = (gm < M && gk < K) ? A[(size_t)gm * lda + gk] : 0.f;
        }
        #pragma unroll
        for (int i = 0; i < (BN * BK) / 256; i++) {
            int idx = tid + i * 256;
            int n = idx >> 4, k = idx & 15;
            int gn = n0 + n, gk = k0 + k;
            Bs[k][n] = (gn < N && gk < K) ? B[(size_t)gn * ldb + gk] : 0.f;
        }
        __syncthreads();

        #pragma unroll
        for (int k = 0; k < BK; k++) {
            float4 a4 = *reinterpret_cast<const float4*>(&As[k][ty * 4]);
            float4 b4 = *reinterpret_cast<const float4*>(&Bs[k][tx * 4]);
            float a[4] = {a4.x, a4.y, a4.z, a4.w};
            float bb[4] = {b4.x, b4.y, b4.z, b4.w};
            #pragma unroll
            for (int i = 0; i < 4; i++)
                #pragma unroll
                for (int j = 0; j < 4; j++)
                    acc[i][j] = fmaf(a[i], bb[j], acc[i][j]);
        }
        __syncthreads();
    }

    #pragma unroll
    for (int i = 0; i < 4; i++) {
        int gm = m0 + ty * 4 + i;
        if (gm >= M) continue;
        #pragma unroll
        for (int j = 0; j < 4; j++) {
            int gn = n0 + tx * 4 + j;
            if (gn >= N) continue;
            float v = acc[i][j];
            if (epi == 1) {
                v += bias[gn];
                // stable softplus: max(x,0) + log1p(exp(-|x|))
                v = fmaxf(v, 0.f) + log1pf(expf(-fabsf(v)));
            } else if (epi == 2) {
                v += resid[(size_t)gm * ldr + gn];
            }
            C[(size_t)gm * ldc + gn] = v;
        }
    }
}

// ---------------- causal depthwise conv (k=4) + SiLU -----------------------
__global__ void conv_silu_kernel(const float* __restrict__ xz,
                                 const float* __restrict__ w,
                                 const float* __restrict__ b,
                                 float* __restrict__ out)
{
    int idx = blockIdx.x * blockDim.x + threadIdx.x;
    if (idx >= NTOK * DI) return;
    int d = idx % DI;
    int r = idx / DI;
    int l = r & (SEQL - 1);
    float acc = b[d];
    const float* wd = w + d * 4;
    #pragma unroll
    for (int j = 0; j < 4; j++) {
        int li = l - 3 + j;
        if (li >= 0)
            acc = fmaf(xz[(size_t)(r - 3 + j) * XZW + d], wd[j], acc);
    }
    out[idx] = acc / (1.f + __expf(-acc));   // silu
}

// ---------------- selective scan: 16 lanes per (b,d) -----------------------
// grid (DI/16, NB), block 256 -> 16 (b,d) groups per block
__global__ void scan_kernel(const float* __restrict__ dt,
                            const float* __restrict__ xs,
                            const float* __restrict__ xdbl,
                            const float* __restrict__ A_log,
                            float* __restrict__ y)
{
    int b = blockIdx.y;
    int d = blockIdx.x * 16 + (threadIdx.x >> 4);
    int n = threadIdx.x & 15;

    float Adn = -__expf(A_log[d * DS + n]);

    size_t rbase = (size_t)b * SEQL;
    const float* dtp = dt   + rbase * DI + d;
    const float* xsp = xs   + rbase * DI + d;
    const float* Bp  = xdbl + rbase * XD + DTR + n;
    const float* Cp  = xdbl + rbase * XD + DTR + DS + n;
    float*       yp  = y    + rbase * DI + d;

    float h = 0.f;
    for (int l = 0; l < SEQL; l++) {
        float dtv = __ldg(dtp); dtp += DI;
        float xv  = __ldg(xsp); xsp += DI;
        float Bv  = __ldg(Bp);  Bp  += XD;
        float Cv  = __ldg(Cp);  Cp  += XD;
        float a = __expf(dtv * Adn);
        h = fmaf(a, h, dtv * xv * Bv);
        float p = h * Cv;
        p += __shfl_xor_sync(0xffffffffu, p, 8);
        p += __shfl_xor_sync(0xffffffffu, p, 4);
        p += __shfl_xor_sync(0xffffffffu, p, 2);
        p += __shfl_xor_sync(0xffffffffu, p, 1);
        if (n == 0) *yp = p;
        yp += DI;
    }
}

// ---------------- gate: y = (y + xs*Dp) * silu(z) ---------------------------
__global__ void gate_kernel(float* __restrict__ y,
                            const float* __restrict__ xs,
                            const float* __restrict__ xz,
                            const float* __restrict__ Dp)
{
    int idx = blockIdx.x * blockDim.x + threadIdx.x;
    if (idx >= NTOK * DI) return;
    int d = idx % DI;
    int r = idx / DI;
    float z = xz[(size_t)r * XZW + DI + d];
    float s = z / (1.f + __expf(-z));
    y[idx] = fmaf(xs[idx], Dp[d], y[idx]) * s;
}

// ---------------- flip along sequence dimension -----------------------------
__global__ void flip_kernel(const float* __restrict__ in, float* __restrict__ out)
{
    int idx = blockIdx.x * blockDim.x + threadIdx.x;
    if (idx >= NTOK * DM) return;
    int d = idx % DM;
    int r = idx / DM;
    int l = r & (SEQL - 1);
    int b = r / SEQL;
    out[idx] = in[((size_t)b * SEQL + (SEQL - 1 - l)) * DM + d];
}

// ---------------- launcher ---------------------------------------------------
extern "C" void kernel_launch(void* const* d_in, const int* in_sizes, int n_in,
                              void* d_out, int out_size)
{
    const float* x        = (const float*)d_in[0];
    const float* norm_w   = (const float*)d_in[1];
    const float* norm_b   = (const float*)d_in[2];
    const float* in_proj  = (const float*)d_in[3];
    const float* conv_w   = (const float*)d_in[4];
    const float* conv_b   = (const float*)d_in[5];
    const float* x_proj   = (const float*)d_in[6];
    const float* dt_w     = (const float*)d_in[7];
    const float* dt_b     = (const float*)d_in[8];
    const float* A_log    = (const float*)d_in[9];
    const float* Dp       = (const float*)d_in[10];
    const float* out_proj = (const float*)d_in[11];

    float *xn, *xz, *xs, *xdbl, *dt, *y, *h1, *h2;
    cudaGetSymbolAddress((void**)&xn,   g_xn);
    cudaGetSymbolAddress((void**)&xz,   g_xz);
    cudaGetSymbolAddress((void**)&xs,   g_xs);
    cudaGetSymbolAddress((void**)&xdbl, g_xdbl);
    cudaGetSymbolAddress((void**)&dt,   g_dt);
    cudaGetSymbolAddress((void**)&y,    g_y);
    cudaGetSymbolAddress((void**)&h1,   g_h1);
    cudaGetSymbolAddress((void**)&h2,   g_h2);

    const int EW = 256;

    for (int i = 0; i < 2; i++) {
        const float* cur = (i == 0) ? x : h2;

        // 1. layernorm
        ln_kernel<<<NTOK, 128>>>(cur, norm_w + i * DM, norm_b + i * DM, xn);

        // 2. xz = xn @ in_proj^T   (M=16384, N=1536, K=384)
        {
            dim3 g((XZW + BN - 1) / BN, (NTOK + BM - 1) / BM);
            gemm_nt<<<g, 256>>>(xn, DM, in_proj + (size_t)i * XZW * DM, DM,
                                xz, XZW, nullptr, nullptr, 0,
                                NTOK, XZW, DM, 0);
        }

        // 3. xs = silu(causal_conv(xz[:, :768]))
        conv_silu_kernel<<<(NTOK * DI + EW - 1) / EW, EW>>>(
            xz, conv_w + (size_t)i * DI * 4, conv_b + i * DI, xs);

        // 4. xdbl = xs @ x_proj^T  (M=16384, N=56, K=768)
        {
            dim3 g((XD + BN - 1) / BN, (NTOK + BM - 1) / BM);
            gemm_nt<<<g, 256>>>(xs, DI, x_proj + (size_t)i * XD * DI, DI,
                                xdbl, XD, nullptr, nullptr, 0,
                                NTOK, XD, DI, 0);
        }

        // 5. dt = softplus(xdbl[:, :24] @ dt_w^T + dt_b)  (M=16384, N=768, K=24)
        {
            dim3 g((DI + BN - 1) / BN, (NTOK + BM - 1) / BM);
            gemm_nt<<<g, 256>>>(xdbl, XD, dt_w + (size_t)i * DI * DTR, DTR,
                                dt, DI, dt_b + i * DI, nullptr, 0,
                                NTOK, DI, DTR, 1);
        }

        // 6. selective scan -> y
        {
            dim3 g(DI / 16, NB);
            scan_kernel<<<g, 256>>>(dt, xs, xdbl,
                                    A_log + (size_t)i * DI * DS, y);
        }

        // 7. gate: y = (y + xs*Dp) * silu(z)
        gate_kernel<<<(NTOK * DI + EW - 1) / EW, EW>>>(y, xs, xz, Dp + i * DI);

        // 8. out = y @ out_proj^T + cur  (M=16384, N=384, K=768)
        {
            dim3 g((DM + BN - 1) / BN, (NTOK + BM - 1) / BM);
            gemm_nt<<<g, 256>>>(y, DI, out_proj + (size_t)i * DM * DI, DI,
                                h1, DM, nullptr, cur, DM,
                                NTOK, DM, DI, 2);
        }

        // 9. flip sequence
        if (i == 0) {
            flip_kernel<<<(NTOK * DM + EW - 1) / EW, EW>>>(h1, h2);
        } else {
            flip_kernel<<<(NTOK * DM + EW - 1) / EW, EW>>>(h1, (float*)d_out);
        }
    }
}

// round 2
// speedup vs baseline: 1.6653x; 1.6653x over previous
#include <cuda_runtime.h>
#include <math.h>
#include <stdint.h>

#define NTOK 16384          // BATCH * SEQ
#define SEQL 2048
#define NB   8
#define DM   384
#define DI   768
#define DS   16
#define DTR  24
#define XD   56             // DTR + 2*DS
#define XZW  1536           // 2*DI

// ---------------- scratch (static device memory; no allocation) ------------
__device__ float g_xn  [(size_t)NTOK * DM];
__device__ float g_xz  [(size_t)NTOK * XZW];
__device__ float g_xs  [(size_t)NTOK * DI];
__device__ float g_xdbl[(size_t)NTOK * XD];
__device__ float g_dt  [(size_t)NTOK * DI];
__device__ float g_y   [(size_t)NTOK * DI];
__device__ float g_h1  [(size_t)NTOK * DM];
__device__ float g_h2  [(size_t)NTOK * DM];

// ---------------- layernorm: one block per token ---------------------------
__global__ void ln_kernel(const float* __restrict__ in,
                          const float* __restrict__ w,
                          const float* __restrict__ b,
                          float* __restrict__ out)
{
    int row = blockIdx.x;
    const float* x = in + (size_t)row * DM;
    int t = threadIdx.x;               // 128 threads, 3 elems each
    float v[3];
    float s = 0.f;
    #pragma unroll
    for (int i = 0; i < 3; i++) { v[i] = x[t + i * 128]; s += v[i]; }

    __shared__ float red[4];
    #pragma unroll
    for (int o = 16; o > 0; o >>= 1) s += __shfl_xor_sync(0xffffffffu, s, o);
    if ((t & 31) == 0) red[t >> 5] = s;
    __syncthreads();
    float mu = (red[0] + red[1] + red[2] + red[3]) * (1.f / 384.f);

    float q = 0.f;
    #pragma unroll
    for (int i = 0; i < 3; i++) { float d = v[i] - mu; q = fmaf(d, d, q); }
    #pragma unroll
    for (int o = 16; o > 0; o >>= 1) q += __shfl_xor_sync(0xffffffffu, q, o);
    __syncthreads();
    if ((t & 31) == 0) red[t >> 5] = q;
    __syncthreads();
    float var = (red[0] + red[1] + red[2] + red[3]) * (1.f / 384.f);
    float rs = rsqrtf(var + 1e-5f);

    float* o = out + (size_t)row * DM;
    #pragma unroll
    for (int i = 0; i < 3; i++) {
        int c = t + i * 128;
        o[c] = (v[i] - mu) * rs * w[c] + b[c];
    }
}

// ================= TF32 tensor-core NT GEMM =================================
// C[m,n] = epi( sum_k A[m,k] * B[n,k] )
// BM=BN=128, BK=32, 256 threads (8 warps as 2x4), warp tile 64x32.
// smem: [row][k] layout, stride BK+4=36 floats (conflict-free fragment LDS).
#define TBM 128
#define TBN 128
#define TBK 32
#define TSTRIDE 36
#define TBUF (TBM * TSTRIDE)   // floats per A (or B) buffer

__device__ __forceinline__ void cp_async16(uint32_t dst, const void* src, bool ok)
{
    int sz = ok ? 16 : 0;
    asm volatile("cp.async.cg.shared.global [%0], [%1], 16, %2;\n"
                 :: "r"(dst), "l"(src), "r"(sz));
}
__device__ __forceinline__ void cp_commit() {
    asm volatile("cp.async.commit_group;\n");
}
__device__ __forceinline__ void cp_wait1() {
    asm volatile("cp.async.wait_group 1;\n");
}
__device__ __forceinline__ uint32_t f2tf32(float f) {
    uint32_t u;
    asm volatile("cvt.rna.tf32.f32 %0, %1;\n" : "=r"(u) : "f"(f));
    return u;
}

// epi: 0 = none, 1 = softplus(v + bias[n]), 2 = v + resid[m*ldr + n]
__global__ void __launch_bounds__(256, 2)
gemm_tf32(const float* __restrict__ A, int lda,
          const float* __restrict__ B, int ldb,
          float* __restrict__ C, int ldc,
          const float* __restrict__ bias,
          const float* __restrict__ resid, int ldr,
          int M, int N, int K, int epi)
{
    extern __shared__ float smem[];
    float* AsB = smem;              // 2 buffers
    float* BsB = smem + 2 * TBUF;

    int tid  = threadIdx.x;
    int lane = tid & 31;
    int warp = tid >> 5;
    int gid  = lane >> 2;      // group id 0..7
    int tig  = lane & 3;       // thread in group 0..3
    int wm   = (warp >> 2) * 64;   // warp m offset (0/64)
    int wn   = (warp & 3) * 32;    // warp n offset (0/32/64/96)

    int m0 = blockIdx.y * TBM;
    int n0 = blockIdx.x * TBN;

    int nc = (K + TBK - 1) / TBK;

    float acc[4][4][4];
    #pragma unroll
    for (int i = 0; i < 4; i++)
        #pragma unroll
        for (int j = 0; j < 4; j++)
            #pragma unroll
            for (int c = 0; c < 4; c++) acc[i][j][c] = 0.f;

    // per-thread load slots: idx = tid + it*256 over 1024 float4 slots
    // m = idx>>3 (0..127), k4 = idx&7 (0..7)
    auto load_tiles = [&](int buf, int chunk) {
        int k0 = chunk * TBK;
        float* Asb = AsB + buf * TBUF;
        float* Bsb = BsB + buf * TBUF;
        #pragma unroll
        for (int it = 0; it < 4; it++) {
            int idx = tid + it * 256;
            int m  = idx >> 3;
            int k4 = idx & 7;
            int gk = k0 + k4 * 4;
            bool kok = (gk < K);
            // A
            {
                int gm = m0 + m;
                const void* src = kok ? (const void*)(A + (size_t)gm * lda + gk)
                                      : (const void*)A;
                uint32_t dst = (uint32_t)__cvta_generic_to_shared(
                                    Asb + m * TSTRIDE + k4 * 4);
                cp_async16(dst, src, kok);
            }
            // B
            {
                int gn = n0 + m;
                bool ok = kok && (gn < N);
                const void* src = ok ? (const void*)(B + (size_t)gn * ldb + gk)
                                     : (const void*)B;
                uint32_t dst = (uint32_t)__cvta_generic_to_shared(
                                    Bsb + m * TSTRIDE + k4 * 4);
                cp_async16(dst, src, ok);
            }
        }
    };

    load_tiles(0, 0);
    cp_commit();

    for (int c = 0; c < nc; c++) {
        if (c + 1 < nc) load_tiles((c + 1) & 1, c + 1);
        cp_commit();
        cp_wait1();
        __syncthreads();

        const float* Asb = AsB + (c & 1) * TBUF;
        const float* Bsb = BsB + (c & 1) * TBUF;

        #pragma unroll
        for (int kk = 0; kk < 4; kk++) {
            int k = kk * 8;
            uint32_t af[4][4];
            #pragma unroll
            for (int mi = 0; mi < 4; mi++) {
                const float* ar0 = Asb + (wm + mi * 16 + gid) * TSTRIDE + k;
                const float* ar1 = Asb + (wm + mi * 16 + gid + 8) * TSTRIDE + k;
                af[mi][0] = f2tf32(ar0[tig]);
                af[mi][1] = f2tf32(ar1[tig]);
                af[mi][2] = f2tf32(ar0[tig + 4]);
                af[mi][3] = f2tf32(ar1[tig + 4]);
            }
            uint32_t bf[4][2];
            #pragma unroll
            for (int ni = 0; ni < 4; ni++) {
                const float* br = Bsb + (wn + ni * 8 + gid) * TSTRIDE + k;
                bf[ni][0] = f2tf32(br[tig]);
                bf[ni][1] = f2tf32(br[tig + 4]);
            }
            #pragma unroll
            for (int mi = 0; mi < 4; mi++)
                #pragma unroll
                for (int ni = 0; ni < 4; ni++) {
                    asm volatile(
                        "mma.sync.aligned.m16n8k8.row.col.f32.tf32.tf32.f32 "
                        "{%0,%1,%2,%3}, {%4,%5,%6,%7}, {%8,%9}, {%0,%1,%2,%3};\n"
                        : "+f"(acc[mi][ni][0]), "+f"(acc[mi][ni][1]),
                          "+f"(acc[mi][ni][2]), "+f"(acc[mi][ni][3])
                        : "r"(af[mi][0]), "r"(af[mi][1]),
                          "r"(af[mi][2]), "r"(af[mi][3]),
                          "r"(bf[ni][0]), "r"(bf[ni][1]));
                }
        }
        __syncthreads();
    }

    // epilogue
    #pragma unroll
    for (int mi = 0; mi < 4; mi++) {
        int r0 = m0 + wm + mi * 16 + gid;
        #pragma unroll
        for (int ni = 0; ni < 4; ni++) {
            int cbase = n0 + wn + ni * 8 + tig * 2;
            #pragma unroll
            for (int half = 0; half < 2; half++) {
                int row = r0 + half * 8;
                if (row >= M) continue;
                #pragma unroll
                for (int cc = 0; cc < 2; cc++) {
                    int col = cbase + cc;
                    if (col >= N) continue;
                    float v = acc[mi][ni][half * 2 + cc];
                    if (epi == 1) {
                        v += bias[col];
                        v = fmaxf(v, 0.f) + log1pf(expf(-fabsf(v)));
                    } else if (epi == 2) {
                        v += resid[(size_t)row * ldr + col];
                    }
                    C[(size_t)row * ldc + col] = v;
                }
            }
        }
    }
}

// ---------------- SIMT NT SGEMM (kept for small-N x_proj) -------------------
#define BM 64
#define BN 64
#define BK 16

__global__ void gemm_nt(const float* __restrict__ A, int lda,
                        const float* __restrict__ B, int ldb,
                        float* __restrict__ C, int ldc,
                        int M, int N, int K)
{
    __shared__ __align__(16) float As[BK][BM + 4];
    __shared__ __align__(16) float Bs[BK][BN + 4];

    int tid = threadIdx.x;           // 256 threads
    int tx = tid & 15, ty = tid >> 4;
    int m0 = blockIdx.y * BM, n0 = blockIdx.x * BN;

    float acc[4][4] = {};

    for (int k0 = 0; k0 < K; k0 += BK) {
        #pragma unroll
        for (int i = 0; i < (BM * BK) / 256; i++) {
            int idx = tid + i * 256;
            int m = idx >> 4, k = idx & 15;
            int gm = m0 + m, gk = k0 + k;
            As[k][m] = (gm < M && gk < K) ? A[(size_t)gm * lda + gk] : 0.f;
        }
        #pragma unroll
        for (int i = 0; i < (BN * BK) / 256; i++) {
            int idx = tid + i * 256;
            int n = idx >> 4, k = idx & 15;
            int gn = n0 + n, gk = k0 + k;
            Bs[k][n] = (gn < N && gk < K) ? B[(size_t)gn * ldb + gk] : 0.f;
        }
        __syncthreads();

        #pragma unroll
        for (int k = 0; k < BK; k++) {
            float4 a4 = *reinterpret_cast<const float4*>(&As[k][ty * 4]);
            float4 b4 = *reinterpret_cast<const float4*>(&Bs[k][tx * 4]);
            float a[4] = {a4.x, a4.y, a4.z, a4.w};
            float bb[4] = {b4.x, b4.y, b4.z, b4.w};
            #pragma unroll
            for (int i = 0; i < 4; i++)
                #pragma unroll
                for (int j = 0; j < 4; j++)
                    acc[i][j] = fmaf(a[i], bb[j], acc[i][j]);
        }
        __syncthreads();
    }

    #pragma unroll
    for (int i = 0; i < 4; i++) {
        int gm = m0 + ty * 4 + i;
        if (gm >= M) continue;
        #pragma unroll
        for (int j = 0; j < 4; j++) {
            int gn = n0 + tx * 4 + j;
            if (gn >= N) continue;
            C[(size_t)gm * ldc + gn] = acc[i][j];
        }
    }
}

// ---------------- causal depthwise conv (k=4) + SiLU -----------------------
__global__ void conv_silu_kernel(const float* __restrict__ xz,
                                 const float* __restrict__ w,
                                 const float* __restrict__ b,
                                 float* __restrict__ out)
{
    int idx = blockIdx.x * blockDim.x + threadIdx.x;
    if (idx >= NTOK * DI) return;
    int d = idx % DI;
    int r = idx / DI;
    int l = r & (SEQL - 1);
    float acc = b[d];
    const float* wd = w + d * 4;
    #pragma unroll
    for (int j = 0; j < 4; j++) {
        int li = l - 3 + j;
        if (li >= 0)
            acc = fmaf(xz[(size_t)(r - 3 + j) * XZW + d], wd[j], acc);
    }
    out[idx] = acc / (1.f + __expf(-acc));   // silu
}

// ---------------- selective scan: 16 lanes per (b,d) -----------------------
__global__ void scan_kernel(const float* __restrict__ dt,
                            const float* __restrict__ xs,
                            const float* __restrict__ xdbl,
                            const float* __restrict__ A_log,
                            float* __restrict__ y)
{
    int b = blockIdx.y;
    int d = blockIdx.x * 16 + (threadIdx.x >> 4);
    int n = threadIdx.x & 15;

    float Adn = -__expf(A_log[d * DS + n]);

    size_t rbase = (size_t)b * SEQL;
    const float* dtp = dt   + rbase * DI + d;
    const float* xsp = xs   + rbase * DI + d;
    const float* Bp  = xdbl + rbase * XD + DTR + n;
    const float* Cp  = xdbl + rbase * XD + DTR + DS + n;
    float*       yp  = y    + rbase * DI + d;

    float h = 0.f;
    for (int l = 0; l < SEQL; l++) {
        float dtv = __ldg(dtp); dtp += DI;
        float xv  = __ldg(xsp); xsp += DI;
        float Bv  = __ldg(Bp);  Bp  += XD;
        float Cv  = __ldg(Cp);  Cp  += XD;
        float a = __expf(dtv * Adn);
        h = fmaf(a, h, dtv * xv * Bv);
        float p = h * Cv;
        p += __shfl_xor_sync(0xffffffffu, p, 8);
        p += __shfl_xor_sync(0xffffffffu, p, 4);
        p += __shfl_xor_sync(0xffffffffu, p, 2);
        p += __shfl_xor_sync(0xffffffffu, p, 1);
        if (n == 0) *yp = p;
        yp += DI;
    }
}

// ---------------- gate: y = (y + xs*Dp) * silu(z) ---------------------------
__global__ void gate_kernel(float* __restrict__ y,
                            const float* __restrict__ xs,
                            const float* __restrict__ xz,
                            const float* __restrict__ Dp)
{
    int idx = blockIdx.x * blockDim.x + threadIdx.x;
    if (idx >= NTOK * DI) return;
    int d = idx % DI;
    int r = idx / DI;
    float z = xz[(size_t)r * XZW + DI + d];
    float s = z / (1.f + __expf(-z));
    y[idx] = fmaf(xs[idx], Dp[d], y[idx]) * s;
}

// ---------------- flip along sequence dimension -----------------------------
__global__ void flip_kernel(const float* __restrict__ in, float* __restrict__ out)
{
    int idx = blockIdx.x * blockDim.x + threadIdx.x;
    if (idx >= NTOK * DM) return;
    int d = idx % DM;
    int r = idx / DM;
    int l = r & (SEQL - 1);
    int b = r / SEQL;
    out[idx] = in[((size_t)b * SEQL + (SEQL - 1 - l)) * DM + d];
}

// ---------------- launcher ---------------------------------------------------
extern "C" void kernel_launch(void* const* d_in, const int* in_sizes, int n_in,
                              void* d_out, int out_size)
{
    const float* x        = (const float*)d_in[0];
    const float* norm_w   = (const float*)d_in[1];
    const float* norm_b   = (const float*)d_in[2];
    const float* in_proj  = (const float*)d_in[3];
    const float* conv_w   = (const float*)d_in[4];
    const float* conv_b   = (const float*)d_in[5];
    const float* x_proj   = (const float*)d_in[6];
    const float* dt_w     = (const float*)d_in[7];
    const float* dt_b     = (const float*)d_in[8];
    const float* A_log    = (const float*)d_in[9];
    const float* Dp       = (const float*)d_in[10];
    const float* out_proj = (const float*)d_in[11];

    float *xn, *xz, *xs, *xdbl, *dt, *y, *h1, *h2;
    cudaGetSymbolAddress((void**)&xn,   g_xn);
    cudaGetSymbolAddress((void**)&xz,   g_xz);
    cudaGetSymbolAddress((void**)&xs,   g_xs);
    cudaGetSymbolAddress((void**)&xdbl, g_xdbl);
    cudaGetSymbolAddress((void**)&dt,   g_dt);
    cudaGetSymbolAddress((void**)&y,    g_y);
    cudaGetSymbolAddress((void**)&h1,   g_h1);
    cudaGetSymbolAddress((void**)&h2,   g_h2);

    const int SMEM_T = 2 * 2 * TBUF * (int)sizeof(float);   // 73728 B
    static int attr_set = 0;
    if (!attr_set) {
        cudaFuncSetAttribute(gemm_tf32,
                             cudaFuncAttributeMaxDynamicSharedMemorySize, SMEM_T);
        attr_set = 1;
    }

    const int EW = 256;

    for (int i = 0; i < 2; i++) {
        const float* cur = (i == 0) ? x : h2;

        // 1. layernorm
        ln_kernel<<<NTOK, 128>>>(cur, norm_w + i * DM, norm_b + i * DM, xn);

        // 2. xz = xn @ in_proj^T   (M=16384, N=1536, K=384)  [tensor]
        {
            dim3 g(XZW / TBN, NTOK / TBM);
            gemm_tf32<<<g, 256, SMEM_T>>>(xn, DM,
                                          in_proj + (size_t)i * XZW * DM, DM,
                                          xz, XZW, nullptr, nullptr, 0,
                                          NTOK, XZW, DM, 0);
        }

        // 3. xs = silu(causal_conv(xz[:, :768]))
        conv_silu_kernel<<<(NTOK * DI + EW - 1) / EW, EW>>>(
            xz, conv_w + (size_t)i * DI * 4, conv_b + i * DI, xs);

        // 4. xdbl = xs @ x_proj^T  (M=16384, N=56, K=768)  [SIMT]
        {
            dim3 g((XD + BN - 1) / BN, (NTOK + BM - 1) / BM);
            gemm_nt<<<g, 256>>>(xs, DI, x_proj + (size_t)i * XD * DI, DI,
                                xdbl, XD, NTOK, XD, DI);
        }

        // 5. dt = softplus(xdbl[:, :24] @ dt_w^T + dt_b)  (N=768, K=24) [tensor]
        {
            dim3 g(DI / TBN, NTOK / TBM);
            gemm_tf32<<<g, 256, SMEM_T>>>(xdbl, XD,
                                          dt_w + (size_t)i * DI * DTR, DTR,
                                          dt, DI, dt_b + i * DI, nullptr, 0,
                                          NTOK, DI, DTR, 1);
        }

        // 6. selective scan -> y
        {
            dim3 g(DI / 16, NB);
            scan_kernel<<<g, 256>>>(dt, xs, xdbl,
                                    A_log + (size_t)i * DI * DS, y);
        }

        // 7. gate: y = (y + xs*Dp) * silu(z)
        gate_kernel<<<(NTOK * DI + EW - 1) / EW, EW>>>(y, xs, xz, Dp + i * DI);

        // 8. out = y @ out_proj^T + cur  (N=384, K=768) [tensor]
        {
            dim3 g(DM / TBN, NTOK / TBM);
            gemm_tf32<<<g, 256, SMEM_T>>>(y, DI,
                                          out_proj + (size_t)i * DM * DI, DI,
                                          h1, DM, nullptr, cur, DM,
                                          NTOK, DM, DI, 2);
        }

        // 9. flip sequence
        if (i == 0) {
            flip_kernel<<<(NTOK * DM + EW - 1) / EW, EW>>>(h1, h2);
        } else {
            flip_kernel<<<(NTOK * DM + EW - 1) / EW, EW>>>(h1, (float*)d_out);
        }
    }
}